// round 2
// baseline (speedup 1.0000x reference)
#include <cuda_runtime.h>
#include <cuda_bf16.h>
#include <cstddef>

#define COL   4096
#define TPB   1024
#define VPT   4           // TPB*VPT == COL, one float4 per thread
#define NWARP (TPB/32)    // 32

// Reciprocal table 1/(i+1), filled each launch (graph-capturable, no allocs).
__device__ float g_rinv[COL];

__global__ void rinv_init_kernel() {
    int i = blockIdx.x * blockDim.x + threadIdx.x;
    if (i < COL) g_rinv[i] = 1.0f / (float)(i + 1);
}

__global__ __launch_bounds__(TPB, 2) void layernorm_v2_kernel(
    const float* __restrict__ x,
    const float* __restrict__ alpha,
    const float* __restrict__ beta,
    float* __restrict__ out)
{
    __shared__ float wsum[NWARP];   // cross-warp scan of per-warp totals
    __shared__ float wvar[NWARP];   // variance partials

    const int row  = blockIdx.x;
    const int tid  = threadIdx.x;
    const int lane = tid & 31;
    const int wid  = tid >> 5;

    // ---- vectorized loads: thread t owns elements [4t, 4t+3] of the row ----
    const float4 xv = ((const float4*)(x + (size_t)row * COL))[tid];
    const float4 rv = ((const float4*)g_rinv)[tid];

    // ---- register-local inclusive scan of the 4-chunk ----
    const float p0 = xv.x;
    const float p1 = p0 + xv.y;
    const float p2 = p1 + xv.z;
    const float p3 = p2 + xv.w;
    const float tot = p3;

    // ---- warp inclusive scan of per-thread totals ----
    float val = tot;
    #pragma unroll
    for (int o = 1; o < 32; o <<= 1) {
        float n = __shfl_up_sync(0xffffffffu, val, o);
        if (lane >= o) val += n;
    }
    if (lane == 31) wsum[wid] = val;
    __syncthreads();

    // ---- cross-warp scan (warp 0 scans the 32 warp totals) ----
    if (wid == 0) {
        float wv = wsum[lane];
        #pragma unroll
        for (int o = 1; o < 32; o <<= 1) {
            float n = __shfl_up_sync(0xffffffffu, wv, o);
            if (lane >= o) wv += n;
        }
        wsum[lane] = wv;
    }
    __syncthreads();

    const float warpoff = (wid > 0) ? wsum[wid - 1] : 0.0f;
    const float excl    = warpoff + val - tot;   // exclusive prefix of this thread
    const float total   = wsum[NWARP - 1];       // full-row sum

    // ---- variance against running mean (all registers) ----
    const float P0 = excl + p0;
    const float P1 = excl + p1;
    const float P2 = excl + p2;
    const float P3 = excl + p3;
    float d0 = xv.x - P0 * rv.x;
    float d1 = xv.y - P1 * rv.y;
    float d2 = xv.z - P2 * rv.z;
    float d3 = xv.w - P3 * rv.w;
    float acc = d0 * d0 + d1 * d1 + d2 * d2 + d3 * d3;

    #pragma unroll
    for (int o = 16; o > 0; o >>= 1) acc += __shfl_xor_sync(0xffffffffu, acc, o);
    if (lane == 0) wvar[wid] = acc;
    __syncthreads();

    // every thread sums the 32 partials (broadcast LDS, 4-way ILP tree)
    float a0 = 0.0f, a1 = 0.0f, a2 = 0.0f, a3 = 0.0f;
    #pragma unroll
    for (int w = 0; w < NWARP; w += 4) {
        a0 += wvar[w + 0];
        a1 += wvar[w + 1];
        a2 += wvar[w + 2];
        a3 += wvar[w + 3];
    }
    const float var  = ((a0 + a1) + (a2 + a3)) * (1.0f / (float)(COL - 1));
    const float mean = total * (1.0f / (float)COL);

    const float al    = __ldg(alpha);
    const float be    = __ldg(beta);
    const float scale = al * rsqrtf(var + 1e-5f);

    // ---- vectorized store ----
    float4 o4;
    o4.x = (xv.x - mean) * scale + be;
    o4.y = (xv.y - mean) * scale + be;
    o4.z = (xv.z - mean) * scale + be;
    o4.w = (xv.w - mean) * scale + be;
    ((float4*)(out + (size_t)row * COL))[tid] = o4;
}

extern "C" void kernel_launch(void* const* d_in, const int* in_sizes, int n_in,
                              void* d_out, int out_size)
{
    const float* x     = (const float*)d_in[0];
    const float* alpha = (const float*)d_in[1];
    const float* beta  = (const float*)d_in[2];
    float*       out   = (float*)d_out;

    const int rows = in_sizes[0] / COL;

    rinv_init_kernel<<<(COL + 255) / 256, 256>>>();
    layernorm_v2_kernel<<<rows, TPB>>>(x, alpha, beta, out);
}

// round 3
// speedup vs baseline: 1.2992x; 1.2992x over previous
#include <cuda_runtime.h>
#include <cuda_bf16.h>
#include <cstddef>

#define COL   4096
#define TPB   512
#define VPT   8            // elements per thread, TPB*VPT == COL
#define NW    (TPB/32)     // 16 warps
#define RPB   8            // rows per block (pipelined)

// Reciprocal table 1/(i+1), filled each launch (graph-capturable, no allocs).
__device__ float g_rinv[COL];

__global__ void rinv_init_kernel() {
    int i = blockIdx.x * blockDim.x + threadIdx.x;
    if (i < COL) g_rinv[i] = 1.0f / (float)(i + 1);
}

__global__ __launch_bounds__(TPB, 2) void layernorm_v2_kernel(
    const float* __restrict__ x,
    const float* __restrict__ alpha,
    const float* __restrict__ beta,
    float* __restrict__ out)
{
    __shared__ float wsum[NW];
    __shared__ float wvar[NW];

    const int tid  = threadIdx.x;
    const int lane = tid & 31;
    const int wid  = tid >> 5;

    // thread t owns elements [8t, 8t+7] -> float4 indices 2t, 2t+1
    const int f4a = 2 * tid;
    const int f4b = 2 * tid + 1;

    // reciprocal table: loaded ONCE per block (amortized over RPB rows)
    const float4 r0 = ((const float4*)g_rinv)[f4a];
    const float4 r1 = ((const float4*)g_rinv)[f4b];

    const float al = __ldg(alpha);
    const float be = __ldg(beta);

    const size_t row0 = (size_t)blockIdx.x * RPB;

    // ---- prologue: load first row ----
    float4 a0 = ((const float4*)(x + row0 * COL))[f4a];
    float4 a1 = ((const float4*)(x + row0 * COL))[f4b];

    #pragma unroll 1
    for (int k = 0; k < RPB; ++k) {
        // ---- prefetch next row BEFORE this row's barriers; LDG issue is not
        //      blocked by BAR.SYNC, so HBM stays busy during the scan phase ----
        float4 b0, b1;
        if (k + 1 < RPB) {
            const float* xn = x + (row0 + k + 1) * COL;
            b0 = ((const float4*)xn)[f4a];
            b1 = ((const float4*)xn)[f4b];
        }

        // ---- register-local inclusive scan of the 8-chunk ----
        const float p0 = a0.x;
        const float p1 = p0 + a0.y;
        const float p2 = p1 + a0.z;
        const float p3 = p2 + a0.w;
        const float p4 = p3 + a1.x;
        const float p5 = p4 + a1.y;
        const float p6 = p5 + a1.z;
        const float p7 = p6 + a1.w;
        const float tot = p7;

        // ---- warp inclusive scan of thread totals ----
        float val = tot;
        #pragma unroll
        for (int o = 1; o < 32; o <<= 1) {
            float n = __shfl_up_sync(0xffffffffu, val, o);
            if (lane >= o) val += n;
        }
        if (lane == 31) wsum[wid] = val;
        __syncthreads();

        // ---- cross-warp scan (warp 0, 16 lanes active) ----
        if (wid == 0) {
            float wv = (lane < NW) ? wsum[lane] : 0.0f;
            #pragma unroll
            for (int o = 1; o < NW; o <<= 1) {
                float n = __shfl_up_sync(0xffffffffu, wv, o);
                if (lane >= o) wv += n;
            }
            if (lane < NW) wsum[lane] = wv;
        }
        __syncthreads();

        const float warpoff = (wid > 0) ? wsum[wid - 1] : 0.0f;
        const float excl    = warpoff + val - tot;
        const float total   = wsum[NW - 1];

        // ---- variance against running mean (registers only) ----
        float d0 = a0.x - (excl + p0) * r0.x;
        float d1 = a0.y - (excl + p1) * r0.y;
        float d2 = a0.z - (excl + p2) * r0.z;
        float d3 = a0.w - (excl + p3) * r0.w;
        float d4 = a1.x - (excl + p4) * r1.x;
        float d5 = a1.y - (excl + p5) * r1.y;
        float d6 = a1.z - (excl + p6) * r1.z;
        float d7 = a1.w - (excl + p7) * r1.w;
        float acc = ((d0 * d0 + d1 * d1) + (d2 * d2 + d3 * d3))
                  + ((d4 * d4 + d5 * d5) + (d6 * d6 + d7 * d7));

        #pragma unroll
        for (int o = 16; o > 0; o >>= 1) acc += __shfl_xor_sync(0xffffffffu, acc, o);
        if (lane == 0) wvar[wid] = acc;
        __syncthreads();

        float s0 = 0.0f, s1 = 0.0f, s2 = 0.0f, s3 = 0.0f;
        #pragma unroll
        for (int w = 0; w < NW; w += 4) {
            s0 += wvar[w + 0];
            s1 += wvar[w + 1];
            s2 += wvar[w + 2];
            s3 += wvar[w + 3];
        }
        const float var   = ((s0 + s1) + (s2 + s3)) * (1.0f / (float)(COL - 1));
        const float mean  = total * (1.0f / (float)COL);
        const float scale = al * rsqrtf(var + 1e-5f);

        // ---- store ----
        float* orow = out + (row0 + k) * COL;
        float4 o4;
        o4.x = (a0.x - mean) * scale + be;
        o4.y = (a0.y - mean) * scale + be;
        o4.z = (a0.z - mean) * scale + be;
        o4.w = (a0.w - mean) * scale + be;
        ((float4*)orow)[f4a] = o4;
        o4.x = (a1.x - mean) * scale + be;
        o4.y = (a1.y - mean) * scale + be;
        o4.z = (a1.z - mean) * scale + be;
        o4.w = (a1.w - mean) * scale + be;
        ((float4*)orow)[f4b] = o4;

        // ---- rotate pipeline ----
        a0 = b0;
        a1 = b1;
    }
}

extern "C" void kernel_launch(void* const* d_in, const int* in_sizes, int n_in,
                              void* d_out, int out_size)
{
    const float* x     = (const float*)d_in[0];
    const float* alpha = (const float*)d_in[1];
    const float* beta  = (const float*)d_in[2];
    float*       out   = (float*)d_out;

    const int rows = in_sizes[0] / COL;
    const int grid = rows / RPB;             // 4096 blocks x 8 rows

    rinv_init_kernel<<<(COL + 255) / 256, 256>>>();
    layernorm_v2_kernel<<<grid, TPB>>>(x, alpha, beta, out);
}